// round 15
// baseline (speedup 1.0000x reference)
#include <cuda_runtime.h>
#include <cuda_bf16.h>
#include <cstdint>

#define TN      128
#define THREADS 256
#define CC      128
#define KD      32

// uint32/float slot offsets in dynamic smem
#define XH_U    0                        // X hi bf16-pairs [128][68]; H hi overlays; XPH packed x pairs for stage 4
#define XL_U    8704                     // X lo ; H lo overlays ; XPL
#define W1H_U   17408                    // W1^T hi pairs [128c][68]; ss overlays after GEMM1
#define SS_F    17408                    // logits fp32 [128][36] -> packed s pairs (in-place)
#define B1_F    26112
#define B2_F    26240
#define IB_I    26272
#define SMEM_U  26400
#define SMEM_BYTES (SMEM_U * 4)          // 105600

#define ZERO_N4 ((64 * KD * CC) / 4)     // 65536
#define R1_N    (CC * 68)                // 8704  : W1 hi pitch array
#define R2_N    (8 * 16 * 2 * 32)        // 8192  : W1 lo frags
#define R3_N    (8 * 4 * 2 * 32)         // 2048  : W2 hi frags
#define R4_N    (8 * 4 * 2 * 32)         // 2048  : W2 lo frags

__device__ uint32_t g_W1h[R1_N];         // pitch-68 hi pairs (smem staging copy)
__device__ uint32_t g_W1Lf[R2_N];        // [ks][cg][e][lane] frag-linear
__device__ uint32_t g_W2Hf[R3_N];        // [js][ng][e][lane]
__device__ uint32_t g_W2Lf[R4_N];

// ---------- helpers ----------
static __device__ __forceinline__ uint32_t smem_u32(const void* p) {
    uint32_t a;
    asm("{ .reg .u64 t; cvta.to.shared.u64 t, %1; cvt.u32.u64 %0, t; }" : "=r"(a) : "l"(p));
    return a;
}
static __device__ __forceinline__ void split_pack(float a, float b, uint32_t& h, uint32_t& l) {
    __nv_bfloat162 th = __floats2bfloat162_rn(a, b);
    uint32_t hp = *(uint32_t*)&th;
    float ha = __uint_as_float(hp << 16);
    float hb = __uint_as_float(hp & 0xFFFF0000u);
    __nv_bfloat162 tl = __floats2bfloat162_rn(a - ha, b - hb);
    h = hp;
    l = *(uint32_t*)&tl;
}
static __device__ __forceinline__ void mma_bf16(float* d, const uint32_t* a,
                                                uint32_t b0, uint32_t b1) {
    asm volatile(
        "mma.sync.aligned.m16n8k16.row.col.f32.bf16.bf16.f32 "
        "{%0,%1,%2,%3}, {%4,%5,%6,%7}, {%8,%9}, {%0,%1,%2,%3};"
        : "+f"(d[0]), "+f"(d[1]), "+f"(d[2]), "+f"(d[3])
        : "r"(a[0]), "r"(a[1]), "r"(a[2]), "r"(a[3]), "r"(b0), "r"(b1));
}
static __device__ __forceinline__ void ldsm_x4(uint32_t* r, uint32_t addr) {
    asm volatile("ldmatrix.sync.aligned.m8n8.x4.shared.b16 {%0,%1,%2,%3}, [%4];"
        : "=r"(r[0]), "=r"(r[1]), "=r"(r[2]), "=r"(r[3]) : "r"(addr));
}

// fused: zero pooled output + all weight pre-splits (pitch array + frag-linear arrays)
__global__ void hp_pre_kernel(float4* __restrict__ o,
                              const float* __restrict__ W1, const float* __restrict__ W2) {
    int idx = blockIdx.x * blockDim.x + threadIdx.x;
    if (idx < ZERO_N4) { o[idx] = make_float4(0.f, 0.f, 0.f, 0.f); return; }
    int i = idx - ZERO_N4;
    uint32_t h, l;
    if (i < R1_N) {
        int c = i / 68, p = i % 68;
        h = 0;
        if (p < 64) {
            split_pack(W1[(2 * p) * CC + c], W1[(2 * p + 1) * CC + c], h, l);
        }
        g_W1h[i] = h;
        return;
    }
    i -= R1_N;
    if (i < R2_N) {
        int lane = i & 31, e = (i >> 5) & 1, cg = (i >> 6) & 15, ks = i >> 10;
        int qc = lane & 3, qr = lane >> 2;
        int k = 16 * ks + 8 * e + 2 * qc;
        int c = 8 * cg + qr;
        split_pack(W1[k * CC + c], W1[(k + 1) * CC + c], h, l);
        g_W1Lf[i] = l;
        return;
    }
    i -= R2_N;
    if (i < R3_N) {
        int lane = i & 31, e = (i >> 5) & 1, ng = (i >> 6) & 3, js = i >> 8;
        int qc = lane & 3, qr = lane >> 2;
        int j = 16 * js + 8 * e + 2 * qc;
        int kb = 8 * ng + qr;
        split_pack(W2[j * KD + kb], W2[(j + 1) * KD + kb], h, l);
        g_W2Hf[i] = h;
        return;
    }
    i -= R3_N;
    if (i < R4_N) {
        int lane = i & 31, e = (i >> 5) & 1, ng = (i >> 6) & 3, js = i >> 8;
        int qc = lane & 3, qr = lane >> 2;
        int j = 16 * js + 8 * e + 2 * qc;
        int kb = 8 * ng + qr;
        split_pack(W2[j * KD + kb], W2[(j + 1) * KD + kb], h, l);
        g_W2Lf[i] = l;
    }
}

__global__ __launch_bounds__(THREADS, 2)
void hp_main_kernel(const float* __restrict__ x, const int* __restrict__ batch,
                    const float* __restrict__ b1, const float* __restrict__ b2,
                    float* __restrict__ out, float* __restrict__ s_out, int N)
{
    extern __shared__ __align__(16) uint32_t smem[];
    uint32_t* XH  = smem + XH_U;                   // pitch 68 (X hi -> H hi); XPH pitch 136
    uint32_t* XL  = smem + XL_U;                   // pitch 68 (X lo -> H lo); XPL pitch 136
    uint32_t* W1H = smem + W1H_U;                  // pitch 68
    float*    ss  = (float*)(smem + SS_F);         // pitch 36 logits -> packed s (in place)
    uint32_t* ssu = smem + SS_F;
    float*    b1s = (float*)(smem + B1_F);
    float*    b2s = (float*)(smem + B2_F);
    int*      ib  = (int*)(smem + IB_I);

    const uint32_t sbase = smem_u32(smem);
    const int tid  = threadIdx.x;
    const int lane = tid & 31;
    const int wid  = tid >> 5;          // 0..7
    const int qr   = lane >> 2;         // 0..7
    const int qc   = lane & 3;          // 0..3
    const int n0   = blockIdx.x * TN;
    const int nvalid = min(TN, N - n0);
    // ldmatrix lane address components: rows 0-15 by lane&15, +16B for k8-15 half
    const uint32_t lrow = (uint32_t)(lane & 15);
    const uint32_t lkof = (lane & 16) ? 16u : 0u;

    // ================= staging =================
    if (tid < TN) ib[tid] = (n0 + tid < N) ? batch[n0 + tid] : -1;
    if (tid < CC) b1s[tid] = b1[tid];
    if (tid < KD) b2s[tid] = b2[tid];
    {
        const float4* xg = (const float4*)x;
        #pragma unroll
        for (int it = 0; it < (TN * 32) / THREADS; ++it) {   // 16
            int idx = it * THREADS + tid;
            int n = idx >> 5, g = idx & 31;
            float4 v = make_float4(0.f, 0.f, 0.f, 0.f);
            if (n < nvalid) v = xg[(size_t)(n0 + n) * 32 + g];
            uint32_t h0, l0, h1, l1;
            split_pack(v.x, v.y, h0, l0);
            split_pack(v.z, v.w, h1, l1);
            XH[n * 68 + 2 * g]     = h0;
            XH[n * 68 + 2 * g + 1] = h1;
            XL[n * 68 + 2 * g]     = l0;
            XL[n * 68 + 2 * g + 1] = l1;
        }
        const float4* s1 = (const float4*)g_W1h;   // 2176 f4
        float4* d1 = (float4*)W1H;
        for (int i = tid; i < R1_N / 4; i += THREADS) d1[i] = s1[i];
    }
    __syncthreads();

    // ===== GEMM1: H = relu(X @ W1 + b1); 3-pass bf16 k16; A via ldmatrix =====
    const int mbase = (wid >> 2) * 64;
    const int cbase = (wid & 3) * 32;
    const int cg0   = (wid & 3) * 4;
    float acc[4][4][4];
    {
        #pragma unroll
        for (int mt = 0; mt < 4; ++mt)
            #pragma unroll
            for (int nt = 0; nt < 4; ++nt)
                #pragma unroll
                for (int e = 0; e < 4; ++e) acc[mt][nt][e] = 0.f;

        // per-lane ldmatrix base address (XH row mbase+lrow, byte offset + lkof)
        const uint32_t aBase = sbase + (XH_U + (mbase + (int)lrow) * 68) * 4 + lkof;

        uint32_t blc[4][2], bln[4][2];
        #pragma unroll
        for (int nt = 0; nt < 4; ++nt) {
            blc[nt][0] = g_W1Lf[((cg0 + nt) * 2) * 32 + lane];
            blc[nt][1] = g_W1Lf[((cg0 + nt) * 2 + 1) * 32 + lane];
        }

        for (int ks = 0; ks < 8; ++ks) {
            const int kb2 = ks * 8;
            uint32_t ah[4][4], al[4][4];
            #pragma unroll
            for (int mt = 0; mt < 4; ++mt) {
                uint32_t a = aBase + mt * (16 * 68 * 4) + ks * 32;
                ldsm_x4(ah[mt], a);
                ldsm_x4(al[mt], a + (XL_U - XH_U) * 4);
            }
            if (ks < 7) {
                #pragma unroll
                for (int nt = 0; nt < 4; ++nt) {
                    int base = ((ks + 1) * 16 + cg0 + nt) * 2;
                    bln[nt][0] = g_W1Lf[base * 32 + lane];
                    bln[nt][1] = g_W1Lf[(base + 1) * 32 + lane];
                }
            }
            #pragma unroll
            for (int nt = 0; nt < 4; ++nt) {
                int cb = cbase + nt * 8 + qr;
                uint32_t bh0 = W1H[cb * 68 + kb2 + qc];
                uint32_t bh1 = W1H[cb * 68 + kb2 + 4 + qc];
                #pragma unroll
                for (int mt = 0; mt < 4; ++mt) {
                    mma_bf16(acc[mt][nt], ah[mt], bh0, bh1);
                    mma_bf16(acc[mt][nt], al[mt], bh0, bh1);
                    mma_bf16(acc[mt][nt], ah[mt], blc[nt][0], blc[nt][1]);
                }
            }
            #pragma unroll
            for (int nt = 0; nt < 4; ++nt) {
                blc[nt][0] = bln[nt][0];
                blc[nt][1] = bln[nt][1];
            }
        }
    }
    __syncthreads();   // all reads of X/W1 tiles done before overlays

    // ---- epilogue 1: relu + bias, write H hi/lo pairs (overlay XH/XL) ----
    {
        #pragma unroll
        for (int mt = 0; mt < 4; ++mt) {
            int r0 = mbase + mt * 16 + qr;
            #pragma unroll
            for (int nt = 0; nt < 4; ++nt) {
                int cb = cbase + nt * 8 + 2 * qc;
                int pidx = (cbase >> 1) + nt * 4 + qc;
                float v0 = fmaxf(acc[mt][nt][0] + b1s[cb], 0.f);
                float v1 = fmaxf(acc[mt][nt][1] + b1s[cb + 1], 0.f);
                float v2 = fmaxf(acc[mt][nt][2] + b1s[cb], 0.f);
                float v3 = fmaxf(acc[mt][nt][3] + b1s[cb + 1], 0.f);
                uint32_t h, l;
                split_pack(v0, v1, h, l);
                XH[r0 * 68 + pidx] = h;
                XL[r0 * 68 + pidx] = l;
                split_pack(v2, v3, h, l);
                XH[(r0 + 8) * 68 + pidx] = h;
                XL[(r0 + 8) * 68 + pidx] = l;
            }
        }
    }
    __syncthreads();

    // ===== GEMM2: logits = H @ W2 + b2; A via ldmatrix; W2 frags double-buffered =====
    {
        const int r0 = wid * 16 + qr;
        const uint32_t aBase = sbase + (XH_U + (wid * 16 + (int)lrow) * 68) * 4 + lkof;
        float a2[4][4];
        #pragma unroll
        for (int nt = 0; nt < 4; ++nt)
            #pragma unroll
            for (int e = 0; e < 4; ++e) a2[nt][e] = 0.f;

        uint32_t whc[4][2], wlc[4][2], whn[4][2], wln[4][2];
        #pragma unroll
        for (int nt = 0; nt < 4; ++nt) {
            whc[nt][0] = g_W2Hf[(nt * 2) * 32 + lane];
            whc[nt][1] = g_W2Hf[(nt * 2 + 1) * 32 + lane];
            wlc[nt][0] = g_W2Lf[(nt * 2) * 32 + lane];
            wlc[nt][1] = g_W2Lf[(nt * 2 + 1) * 32 + lane];
        }

        for (int js = 0; js < 8; ++js) {
            uint32_t ah[4], al[4];
            uint32_t a = aBase + js * 32;
            ldsm_x4(ah, a);
            ldsm_x4(al, a + (XL_U - XH_U) * 4);
            if (js < 7) {
                #pragma unroll
                for (int nt = 0; nt < 4; ++nt) {
                    int base = ((js + 1) * 4 + nt) * 2;
                    whn[nt][0] = g_W2Hf[base * 32 + lane];
                    whn[nt][1] = g_W2Hf[(base + 1) * 32 + lane];
                    wln[nt][0] = g_W2Lf[base * 32 + lane];
                    wln[nt][1] = g_W2Lf[(base + 1) * 32 + lane];
                }
            }
            #pragma unroll
            for (int nt = 0; nt < 4; ++nt) {
                mma_bf16(a2[nt], ah, whc[nt][0], whc[nt][1]);
                mma_bf16(a2[nt], al, whc[nt][0], whc[nt][1]);
                mma_bf16(a2[nt], ah, wlc[nt][0], wlc[nt][1]);
            }
            #pragma unroll
            for (int nt = 0; nt < 4; ++nt) {
                whc[nt][0] = whn[nt][0]; whc[nt][1] = whn[nt][1];
                wlc[nt][0] = wln[nt][0]; wlc[nt][1] = wln[nt][1];
            }
        }
        #pragma unroll
        for (int nt = 0; nt < 4; ++nt) {
            int kb = nt * 8 + 2 * qc;
            *(float2*)&ss[r0 * 36 + kb] =
                make_float2(a2[nt][0] + b2s[kb], a2[nt][1] + b2s[kb + 1]);
            *(float2*)&ss[(r0 + 8) * 36 + kb] =
                make_float2(a2[nt][2] + b2s[kb], a2[nt][3] + b2s[kb + 1]);
        }
    }
    __syncthreads();

    // ===== merged phase: softmax (packed in-place) + x reload as packed pairs =====
    {
        #pragma unroll
        for (int i8 = 0; i8 < 8; ++i8) {
            int n = wid * 16 + 2 * i8;
            float v0 = ss[n * 36 + lane];
            float v1 = ss[(n + 1) * 36 + lane];
            float m0v = v0, m1v = v1;
            #pragma unroll
            for (int o = 16; o > 0; o >>= 1) {
                m0v = fmaxf(m0v, __shfl_xor_sync(0xffffffffu, m0v, o));
                m1v = fmaxf(m1v, __shfl_xor_sync(0xffffffffu, m1v, o));
            }
            float e0 = __expf(v0 - m0v);
            float e1 = __expf(v1 - m1v);
            float s0 = e0, s1 = e1;
            #pragma unroll
            for (int o = 16; o > 0; o >>= 1) {
                s0 += __shfl_xor_sync(0xffffffffu, s0, o);
                s1 += __shfl_xor_sync(0xffffffffu, s1, o);
            }
            float sv0 = e0 / s0;
            float sv1 = e1 / s1;
            if (n < nvalid)     s_out[(size_t)(n0 + n) * KD + lane] = sv0;
            if (n + 1 < nvalid) s_out[(size_t)(n0 + n + 1) * KD + lane] = sv1;
            uint32_t h, l;
            split_pack(sv0, sv1, h, l);
            ssu[n * 36 + lane]       = h;
            ssu[(n + 1) * 36 + lane] = l;
        }
        // x reload as packed bf16 node-pairs into dead H region (split once)
        const float4* xg = (const float4*)x;
        #pragma unroll
        for (int it = 0; it < 8; ++it) {
            int idx = it * THREADS + tid;
            int p = idx >> 5, g = idx & 31;
            float4 v0 = make_float4(0.f, 0.f, 0.f, 0.f);
            float4 v1 = v0;
            if (2 * p < nvalid)     v0 = xg[(size_t)(n0 + 2 * p) * 32 + g];
            if (2 * p + 1 < nvalid) v1 = xg[(size_t)(n0 + 2 * p + 1) * 32 + g];
            uint32_t h0, l0, h1, l1, h2, l2, h3, l3;
            split_pack(v0.x, v1.x, h0, l0);
            split_pack(v0.y, v1.y, h1, l1);
            split_pack(v0.z, v1.z, h2, l2);
            split_pack(v0.w, v1.w, h3, l3);
            *(uint4*)&XH[p * 136 + 4 * g] = make_uint4(h0, h1, h2, h3);
            *(uint4*)&XL[p * 136 + 4 * g] = make_uint4(l0, l1, l2, l3);
        }
    }
    __syncthreads();

    // ===== stage 4 as GEMM: P[m=32][c=128] = S^T @ X per segment, 3-pass bf16 mma =====
    {
        const int mo = (wid >> 2) * 16;
        const int cq = (wid & 3) * 32;
        const int m0 = mo + qr;                  // D rows m0, m0+8
        const int bmin = ib[0];
        const int bmax = ib[nvalid - 1];
        const bool multi = (bmin != bmax);

        for (int b = bmin; b <= bmax; ++b) {
            float pacc[4][4];
            #pragma unroll
            for (int nt = 0; nt < 4; ++nt)
                #pragma unroll
                for (int e = 0; e < 4; ++e) pacc[nt][e] = 0.f;

            for (int ks = 0; ks < 8; ++ks) {
                const int pr0 = ks * 8 + qc;     // node pairs this lane touches
                const int pr1 = pr0 + 4;

                uint32_t aH[4], aL[4];
                aH[0] = ssu[pr0 * 72 + m0];
                aH[1] = ssu[pr0 * 72 + m0 + 8];
                aH[2] = ssu[pr1 * 72 + m0];
                aH[3] = ssu[pr1 * 72 + m0 + 8];
                aL[0] = ssu[pr0 * 72 + 36 + m0];
                aL[1] = ssu[pr0 * 72 + 36 + m0 + 8];
                aL[2] = ssu[pr1 * 72 + 36 + m0];
                aL[3] = ssu[pr1 * 72 + 36 + m0 + 8];
                if (multi) {
                    uint32_t msk0 = (ib[2 * pr0]     != b ? 0xFFFF0000u : 0xFFFFFFFFu)
                                  & (ib[2 * pr0 + 1] != b ? 0x0000FFFFu : 0xFFFFFFFFu);
                    uint32_t msk1 = (ib[2 * pr1]     != b ? 0xFFFF0000u : 0xFFFFFFFFu)
                                  & (ib[2 * pr1 + 1] != b ? 0x0000FFFFu : 0xFFFFFFFFu);
                    aH[0] &= msk0; aH[1] &= msk0; aL[0] &= msk0; aL[1] &= msk0;
                    aH[2] &= msk1; aH[3] &= msk1; aL[2] &= msk1; aL[3] &= msk1;
                }

                #pragma unroll
                for (int nt = 0; nt < 4; ++nt) {
                    int c = cq + nt * 8 + qr;        // B column
                    uint32_t bh0 = XH[pr0 * 136 + c];
                    uint32_t bh1 = XH[pr1 * 136 + c];
                    uint32_t bl0 = XL[pr0 * 136 + c];
                    uint32_t bl1 = XL[pr1 * 136 + c];
                    mma_bf16(pacc[nt], aH, bh0, bh1);
                    mma_bf16(pacc[nt], aL, bh0, bh1);
                    mma_bf16(pacc[nt], aH, bl0, bl1);
                }
            }
            float* ob = out + (size_t)b * (KD * CC);
            #pragma unroll
            for (int nt = 0; nt < 4; ++nt) {
                int c = cq + nt * 8 + 2 * qc;
                atomicAdd(&ob[m0 * CC + c],           pacc[nt][0]);
                atomicAdd(&ob[m0 * CC + c + 1],       pacc[nt][1]);
                atomicAdd(&ob[(m0 + 8) * CC + c],     pacc[nt][2]);
                atomicAdd(&ob[(m0 + 8) * CC + c + 1], pacc[nt][3]);
            }
        }
    }
}

extern "C" void kernel_launch(void* const* d_in, const int* in_sizes, int n_in,
                              void* d_out, int out_size)
{
    const float* x     = (const float*)d_in[0];
    const int*   batch = (const int*)d_in[1];
    const float* W1    = (const float*)d_in[2];
    const float* b1    = (const float*)d_in[3];
    const float* W2    = (const float*)d_in[4];
    const float* b2    = (const float*)d_in[5];

    const int N = in_sizes[1];
    float* out = (float*)d_out;
    size_t out_elems = (size_t)out_size - (size_t)N * KD;   // B*K*C
    float* s_out = out + out_elems;

    {   // fused zero + weight prep (one launch)
        int total = ZERO_N4 + R1_N + R2_N + R3_N + R4_N;
        hp_pre_kernel<<<(total + 255) / 256, 256>>>((float4*)out, W1, W2);
    }

    cudaFuncSetAttribute(hp_main_kernel,
                         cudaFuncAttributeMaxDynamicSharedMemorySize, SMEM_BYTES);
    int nb = (N + TN - 1) / TN;
    hp_main_kernel<<<nb, THREADS, SMEM_BYTES>>>(x, batch, b1, b2, out, s_out, N);
}

// round 16
// speedup vs baseline: 1.1011x; 1.1011x over previous
#include <cuda_runtime.h>
#include <cuda_bf16.h>
#include <cuda_fp16.h>
#include <cstdint>

#define TN      128
#define THREADS 256
#define CC      128
#define KD      32

// uint32/float slot offsets in dynamic smem
#define XH_U    0                        // X hi bf16-pairs [128][68]; H hi overlays; XPH fp16 x pairs for stage 4
#define XL_U    8704                     // X lo ; H lo overlays
#define W1H_U   17408                    // W1^T hi pairs [128c][68]; ss overlays after GEMM1
#define SS_F    17408                    // logits fp32 [128][36] -> packed fp16 s pairs (in-place)
#define B1_F    26112
#define B2_F    26240
#define IB_I    26272
#define SMEM_U  26400
#define SMEM_BYTES (SMEM_U * 4)          // 105600

#define ZERO_N4 ((64 * KD * CC) / 4)     // 65536
#define R1_N    (CC * 68)                // 8704  : W1 hi pitch array
#define R2_N    (8 * 16 * 2 * 32)        // 8192  : W1 lo frags
#define R3_N    (8 * 4 * 2 * 32)         // 2048  : W2 hi frags
#define R4_N    (8 * 4 * 2 * 32)         // 2048  : W2 lo frags

__device__ uint32_t g_W1h[R1_N];         // pitch-68 hi pairs (smem staging copy)
__device__ uint32_t g_W1Lf[R2_N];        // [ks][cg][e][lane] frag-linear
__device__ uint32_t g_W2Hf[R3_N];        // [js][ng][e][lane]
__device__ uint32_t g_W2Lf[R4_N];

// ---------- helpers ----------
static __device__ __forceinline__ void split_pack(float a, float b, uint32_t& h, uint32_t& l) {
    __nv_bfloat162 th = __floats2bfloat162_rn(a, b);
    uint32_t hp = *(uint32_t*)&th;
    float ha = __uint_as_float(hp << 16);
    float hb = __uint_as_float(hp & 0xFFFF0000u);
    __nv_bfloat162 tl = __floats2bfloat162_rn(a - ha, b - hb);
    h = hp;
    l = *(uint32_t*)&tl;
}
static __device__ __forceinline__ uint32_t pk_h2(float a, float b) {
    __half2 t = __floats2half2_rn(a, b);
    return *(uint32_t*)&t;
}
static __device__ __forceinline__ void mma_bf16(float* d, const uint32_t* a,
                                                uint32_t b0, uint32_t b1) {
    asm volatile(
        "mma.sync.aligned.m16n8k16.row.col.f32.bf16.bf16.f32 "
        "{%0,%1,%2,%3}, {%4,%5,%6,%7}, {%8,%9}, {%0,%1,%2,%3};"
        : "+f"(d[0]), "+f"(d[1]), "+f"(d[2]), "+f"(d[3])
        : "r"(a[0]), "r"(a[1]), "r"(a[2]), "r"(a[3]), "r"(b0), "r"(b1));
}
static __device__ __forceinline__ void mma_f16(float* d, const uint32_t* a,
                                               uint32_t b0, uint32_t b1) {
    asm volatile(
        "mma.sync.aligned.m16n8k16.row.col.f32.f16.f16.f32 "
        "{%0,%1,%2,%3}, {%4,%5,%6,%7}, {%8,%9}, {%0,%1,%2,%3};"
        : "+f"(d[0]), "+f"(d[1]), "+f"(d[2]), "+f"(d[3])
        : "r"(a[0]), "r"(a[1]), "r"(a[2]), "r"(a[3]), "r"(b0), "r"(b1));
}

// fused: zero pooled output + all weight pre-splits (pitch array + frag-linear arrays)
__global__ void hp_pre_kernel(float4* __restrict__ o,
                              const float* __restrict__ W1, const float* __restrict__ W2) {
    int idx = blockIdx.x * blockDim.x + threadIdx.x;
    if (idx < ZERO_N4) { o[idx] = make_float4(0.f, 0.f, 0.f, 0.f); return; }
    int i = idx - ZERO_N4;
    uint32_t h, l;
    if (i < R1_N) {
        int c = i / 68, p = i % 68;
        h = 0;
        if (p < 64) {
            split_pack(W1[(2 * p) * CC + c], W1[(2 * p + 1) * CC + c], h, l);
        }
        g_W1h[i] = h;
        return;
    }
    i -= R1_N;
    if (i < R2_N) {
        int lane = i & 31, e = (i >> 5) & 1, cg = (i >> 6) & 15, ks = i >> 10;
        int qc = lane & 3, qr = lane >> 2;
        int k = 16 * ks + 8 * e + 2 * qc;
        int c = 8 * cg + qr;
        split_pack(W1[k * CC + c], W1[(k + 1) * CC + c], h, l);
        g_W1Lf[i] = l;
        return;
    }
    i -= R2_N;
    if (i < R3_N) {
        int lane = i & 31, e = (i >> 5) & 1, ng = (i >> 6) & 3, js = i >> 8;
        int qc = lane & 3, qr = lane >> 2;
        int j = 16 * js + 8 * e + 2 * qc;
        int kb = 8 * ng + qr;
        split_pack(W2[j * KD + kb], W2[(j + 1) * KD + kb], h, l);
        g_W2Hf[i] = h;
        return;
    }
    i -= R3_N;
    if (i < R4_N) {
        int lane = i & 31, e = (i >> 5) & 1, ng = (i >> 6) & 3, js = i >> 8;
        int qc = lane & 3, qr = lane >> 2;
        int j = 16 * js + 8 * e + 2 * qc;
        int kb = 8 * ng + qr;
        split_pack(W2[j * KD + kb], W2[(j + 1) * KD + kb], h, l);
        g_W2Lf[i] = l;
    }
}

__global__ __launch_bounds__(THREADS, 2)
void hp_main_kernel(const float* __restrict__ x, const int* __restrict__ batch,
                    const float* __restrict__ b1, const float* __restrict__ b2,
                    float* __restrict__ out, float* __restrict__ s_out, int N)
{
    extern __shared__ __align__(16) uint32_t smem[];
    uint32_t* XH  = smem + XH_U;                   // pitch 68 (X hi -> H hi); XPH fp16 pitch 136
    uint32_t* XL  = smem + XL_U;                   // pitch 68 (X lo -> H lo)
    uint32_t* W1H = smem + W1H_U;                  // pitch 68
    float*    ss  = (float*)(smem + SS_F);         // pitch 36 logits -> packed fp16 s (in place)
    uint32_t* ssu = smem + SS_F;
    float*    b1s = (float*)(smem + B1_F);
    float*    b2s = (float*)(smem + B2_F);
    int*      ib  = (int*)(smem + IB_I);

    const int tid  = threadIdx.x;
    const int lane = tid & 31;
    const int wid  = tid >> 5;          // 0..7
    const int qr   = lane >> 2;         // 0..7
    const int qc   = lane & 3;          // 0..3
    const int n0   = blockIdx.x * TN;
    const int nvalid = min(TN, N - n0);

    // ================= staging =================
    if (tid < TN) ib[tid] = (n0 + tid < N) ? batch[n0 + tid] : -1;
    if (tid < CC) b1s[tid] = b1[tid];
    if (tid < KD) b2s[tid] = b2[tid];
    {
        const float4* xg = (const float4*)x;
        #pragma unroll
        for (int it = 0; it < (TN * 32) / THREADS; ++it) {   // 16
            int idx = it * THREADS + tid;
            int n = idx >> 5, g = idx & 31;
            float4 v = make_float4(0.f, 0.f, 0.f, 0.f);
            if (n < nvalid) v = xg[(size_t)(n0 + n) * 32 + g];
            uint32_t h0, l0, h1, l1;
            split_pack(v.x, v.y, h0, l0);
            split_pack(v.z, v.w, h1, l1);
            XH[n * 68 + 2 * g]     = h0;
            XH[n * 68 + 2 * g + 1] = h1;
            XL[n * 68 + 2 * g]     = l0;
            XL[n * 68 + 2 * g + 1] = l1;
        }
        const float4* s1 = (const float4*)g_W1h;   // 2176 f4
        float4* d1 = (float4*)W1H;
        for (int i = tid; i < R1_N / 4; i += THREADS) d1[i] = s1[i];
    }
    __syncthreads();

    // ===== GEMM1: H = relu(X @ W1 + b1); 3-pass bf16 k16; W1-lo frags from global =====
    const int mbase = (wid >> 2) * 64;
    const int cbase = (wid & 3) * 32;
    const int cg0   = (wid & 3) * 4;
    float acc[4][4][4];
    {
        #pragma unroll
        for (int mt = 0; mt < 4; ++mt)
            #pragma unroll
            for (int nt = 0; nt < 4; ++nt)
                #pragma unroll
                for (int e = 0; e < 4; ++e) acc[mt][nt][e] = 0.f;

        uint32_t blc[4][2], bln[4][2];
        #pragma unroll
        for (int nt = 0; nt < 4; ++nt) {
            blc[nt][0] = g_W1Lf[((cg0 + nt) * 2) * 32 + lane];
            blc[nt][1] = g_W1Lf[((cg0 + nt) * 2 + 1) * 32 + lane];
        }

        for (int ks = 0; ks < 8; ++ks) {
            const int kb2 = ks * 8;
            uint32_t ah[4][4], al[4][4];
            #pragma unroll
            for (int mt = 0; mt < 4; ++mt) {
                int r0 = mbase + mt * 16 + qr;
                ah[mt][0] = XH[r0 * 68 + kb2 + qc];
                ah[mt][1] = XH[(r0 + 8) * 68 + kb2 + qc];
                ah[mt][2] = XH[r0 * 68 + kb2 + 4 + qc];
                ah[mt][3] = XH[(r0 + 8) * 68 + kb2 + 4 + qc];
                al[mt][0] = XL[r0 * 68 + kb2 + qc];
                al[mt][1] = XL[(r0 + 8) * 68 + kb2 + qc];
                al[mt][2] = XL[r0 * 68 + kb2 + 4 + qc];
                al[mt][3] = XL[(r0 + 8) * 68 + kb2 + 4 + qc];
            }
            if (ks < 7) {
                #pragma unroll
                for (int nt = 0; nt < 4; ++nt) {
                    int base = ((ks + 1) * 16 + cg0 + nt) * 2;
                    bln[nt][0] = g_W1Lf[base * 32 + lane];
                    bln[nt][1] = g_W1Lf[(base + 1) * 32 + lane];
                }
            }
            #pragma unroll
            for (int nt = 0; nt < 4; ++nt) {
                int cb = cbase + nt * 8 + qr;
                uint32_t bh0 = W1H[cb * 68 + kb2 + qc];
                uint32_t bh1 = W1H[cb * 68 + kb2 + 4 + qc];
                #pragma unroll
                for (int mt = 0; mt < 4; ++mt) {
                    mma_bf16(acc[mt][nt], ah[mt], bh0, bh1);
                    mma_bf16(acc[mt][nt], al[mt], bh0, bh1);
                    mma_bf16(acc[mt][nt], ah[mt], blc[nt][0], blc[nt][1]);
                }
            }
            #pragma unroll
            for (int nt = 0; nt < 4; ++nt) {
                blc[nt][0] = bln[nt][0];
                blc[nt][1] = bln[nt][1];
            }
        }
    }
    __syncthreads();   // all reads of X/W1 tiles done before overlays

    // ---- epilogue 1: relu + bias, write H hi/lo pairs (overlay XH/XL) ----
    {
        #pragma unroll
        for (int mt = 0; mt < 4; ++mt) {
            int r0 = mbase + mt * 16 + qr;
            #pragma unroll
            for (int nt = 0; nt < 4; ++nt) {
                int cb = cbase + nt * 8 + 2 * qc;
                int pidx = (cbase >> 1) + nt * 4 + qc;
                float v0 = fmaxf(acc[mt][nt][0] + b1s[cb], 0.f);
                float v1 = fmaxf(acc[mt][nt][1] + b1s[cb + 1], 0.f);
                float v2 = fmaxf(acc[mt][nt][2] + b1s[cb], 0.f);
                float v3 = fmaxf(acc[mt][nt][3] + b1s[cb + 1], 0.f);
                uint32_t h, l;
                split_pack(v0, v1, h, l);
                XH[r0 * 68 + pidx] = h;
                XL[r0 * 68 + pidx] = l;
                split_pack(v2, v3, h, l);
                XH[(r0 + 8) * 68 + pidx] = h;
                XL[(r0 + 8) * 68 + pidx] = l;
            }
        }
    }
    __syncthreads();

    // ===== GEMM2: logits = H @ W2 + b2; W2 frags from global, double-buffered =====
    {
        const int r0 = wid * 16 + qr;
        float a2[4][4];
        #pragma unroll
        for (int nt = 0; nt < 4; ++nt)
            #pragma unroll
            for (int e = 0; e < 4; ++e) a2[nt][e] = 0.f;

        uint32_t whc[4][2], wlc[4][2], whn[4][2], wln[4][2];
        #pragma unroll
        for (int nt = 0; nt < 4; ++nt) {
            whc[nt][0] = g_W2Hf[(nt * 2) * 32 + lane];
            whc[nt][1] = g_W2Hf[(nt * 2 + 1) * 32 + lane];
            wlc[nt][0] = g_W2Lf[(nt * 2) * 32 + lane];
            wlc[nt][1] = g_W2Lf[(nt * 2 + 1) * 32 + lane];
        }

        for (int js = 0; js < 8; ++js) {
            const int jb2 = js * 8;
            uint32_t ah[4], al[4];
            ah[0] = XH[r0 * 68 + jb2 + qc];
            ah[1] = XH[(r0 + 8) * 68 + jb2 + qc];
            ah[2] = XH[r0 * 68 + jb2 + 4 + qc];
            ah[3] = XH[(r0 + 8) * 68 + jb2 + 4 + qc];
            al[0] = XL[r0 * 68 + jb2 + qc];
            al[1] = XL[(r0 + 8) * 68 + jb2 + qc];
            al[2] = XL[r0 * 68 + jb2 + 4 + qc];
            al[3] = XL[(r0 + 8) * 68 + jb2 + 4 + qc];
            if (js < 7) {
                #pragma unroll
                for (int nt = 0; nt < 4; ++nt) {
                    int base = ((js + 1) * 4 + nt) * 2;
                    whn[nt][0] = g_W2Hf[base * 32 + lane];
                    whn[nt][1] = g_W2Hf[(base + 1) * 32 + lane];
                    wln[nt][0] = g_W2Lf[base * 32 + lane];
                    wln[nt][1] = g_W2Lf[(base + 1) * 32 + lane];
                }
            }
            #pragma unroll
            for (int nt = 0; nt < 4; ++nt) {
                mma_bf16(a2[nt], ah, whc[nt][0], whc[nt][1]);
                mma_bf16(a2[nt], al, whc[nt][0], whc[nt][1]);
                mma_bf16(a2[nt], ah, wlc[nt][0], wlc[nt][1]);
            }
            #pragma unroll
            for (int nt = 0; nt < 4; ++nt) {
                whc[nt][0] = whn[nt][0]; whc[nt][1] = whn[nt][1];
                wlc[nt][0] = wln[nt][0]; wlc[nt][1] = wln[nt][1];
            }
        }
        #pragma unroll
        for (int nt = 0; nt < 4; ++nt) {
            int kb = nt * 8 + 2 * qc;
            *(float2*)&ss[r0 * 36 + kb] =
                make_float2(a2[nt][0] + b2s[kb], a2[nt][1] + b2s[kb + 1]);
            *(float2*)&ss[(r0 + 8) * 36 + kb] =
                make_float2(a2[nt][2] + b2s[kb], a2[nt][3] + b2s[kb + 1]);
        }
    }
    __syncthreads();

    // ===== merged phase: softmax (fp16 pack in-place) + x reload as fp16 pairs =====
    {
        #pragma unroll
        for (int i8 = 0; i8 < 8; ++i8) {
            int n = wid * 16 + 2 * i8;
            float v0 = ss[n * 36 + lane];
            float v1 = ss[(n + 1) * 36 + lane];
            float m0v = v0, m1v = v1;
            #pragma unroll
            for (int o = 16; o > 0; o >>= 1) {
                m0v = fmaxf(m0v, __shfl_xor_sync(0xffffffffu, m0v, o));
                m1v = fmaxf(m1v, __shfl_xor_sync(0xffffffffu, m1v, o));
            }
            float e0 = __expf(v0 - m0v);
            float e1 = __expf(v1 - m1v);
            float s0 = e0, s1 = e1;
            #pragma unroll
            for (int o = 16; o > 0; o >>= 1) {
                s0 += __shfl_xor_sync(0xffffffffu, s0, o);
                s1 += __shfl_xor_sync(0xffffffffu, s1, o);
            }
            float sv0 = e0 / s0;
            float sv1 = e1 / s1;
            if (n < nvalid)     s_out[(size_t)(n0 + n) * KD + lane] = sv0;
            if (n + 1 < nvalid) s_out[(size_t)(n0 + n + 1) * KD + lane] = sv1;
            ssu[n * 36 + lane] = pk_h2(sv0, sv1);   // fp16 pair, hi row only
        }
        // x reload as fp16 node-pairs into dead H-hi region (XPH [64][136])
        const float4* xg = (const float4*)x;
        #pragma unroll
        for (int it = 0; it < 8; ++it) {
            int idx = it * THREADS + tid;
            int p = idx >> 5, g = idx & 31;
            float4 v0 = make_float4(0.f, 0.f, 0.f, 0.f);
            float4 v1 = v0;
            if (2 * p < nvalid)     v0 = xg[(size_t)(n0 + 2 * p) * 32 + g];
            if (2 * p + 1 < nvalid) v1 = xg[(size_t)(n0 + 2 * p + 1) * 32 + g];
            *(uint4*)&XH[p * 136 + 4 * g] = make_uint4(
                pk_h2(v0.x, v1.x), pk_h2(v0.y, v1.y),
                pk_h2(v0.z, v1.z), pk_h2(v0.w, v1.w));
        }
    }
    __syncthreads();

    // ===== stage 4 as GEMM: P[m=32][c=128] = S^T @ X per segment, 1-pass fp16 mma =====
    {
        const int mo = (wid >> 2) * 16;
        const int cq = (wid & 3) * 32;
        const int m0 = mo + qr;                  // D rows m0, m0+8
        const int bmin = ib[0];
        const int bmax = ib[nvalid - 1];
        const bool multi = (bmin != bmax);

        for (int b = bmin; b <= bmax; ++b) {
            float pacc[4][4];
            #pragma unroll
            for (int nt = 0; nt < 4; ++nt)
                #pragma unroll
                for (int e = 0; e < 4; ++e) pacc[nt][e] = 0.f;

            for (int ks = 0; ks < 8; ++ks) {
                const int pr0 = ks * 8 + qc;     // node pairs this lane touches
                const int pr1 = pr0 + 4;

                uint32_t aH[4];
                aH[0] = ssu[pr0 * 72 + m0];
                aH[1] = ssu[pr0 * 72 + m0 + 8];
                aH[2] = ssu[pr1 * 72 + m0];
                aH[3] = ssu[pr1 * 72 + m0 + 8];
                if (multi) {
                    uint32_t msk0 = (ib[2 * pr0]     != b ? 0xFFFF0000u : 0xFFFFFFFFu)
                                  & (ib[2 * pr0 + 1] != b ? 0x0000FFFFu : 0xFFFFFFFFu);
                    uint32_t msk1 = (ib[2 * pr1]     != b ? 0xFFFF0000u : 0xFFFFFFFFu)
                                  & (ib[2 * pr1 + 1] != b ? 0x0000FFFFu : 0xFFFFFFFFu);
                    aH[0] &= msk0; aH[1] &= msk0;
                    aH[2] &= msk1; aH[3] &= msk1;
                }

                #pragma unroll
                for (int nt = 0; nt < 4; ++nt) {
                    int c = cq + nt * 8 + qr;        // B column
                    uint32_t bh0 = XH[pr0 * 136 + c];
                    uint32_t bh1 = XH[pr1 * 136 + c];
                    mma_f16(pacc[nt], aH, bh0, bh1);
                }
            }
            float* ob = out + (size_t)b * (KD * CC);
            #pragma unroll
            for (int nt = 0; nt < 4; ++nt) {
                int c = cq + nt * 8 + 2 * qc;
                atomicAdd(&ob[m0 * CC + c],           pacc[nt][0]);
                atomicAdd(&ob[m0 * CC + c + 1],       pacc[nt][1]);
                atomicAdd(&ob[(m0 + 8) * CC + c],     pacc[nt][2]);
                atomicAdd(&ob[(m0 + 8) * CC + c + 1], pacc[nt][3]);
            }
        }
    }
}

extern "C" void kernel_launch(void* const* d_in, const int* in_sizes, int n_in,
                              void* d_out, int out_size)
{
    const float* x     = (const float*)d_in[0];
    const int*   batch = (const int*)d_in[1];
    const float* W1    = (const float*)d_in[2];
    const float* b1    = (const float*)d_in[3];
    const float* W2    = (const float*)d_in[4];
    const float* b2    = (const float*)d_in[5];

    const int N = in_sizes[1];
    float* out = (float*)d_out;
    size_t out_elems = (size_t)out_size - (size_t)N * KD;   // B*K*C
    float* s_out = out + out_elems;

    {   // fused zero + weight prep (one launch)
        int total = ZERO_N4 + R1_N + R2_N + R3_N + R4_N;
        hp_pre_kernel<<<(total + 255) / 256, 256>>>((float4*)out, W1, W2);
    }

    cudaFuncSetAttribute(hp_main_kernel,
                         cudaFuncAttributeMaxDynamicSharedMemorySize, SMEM_BYTES);
    int nb = (N + TN - 1) / TN;
    hp_main_kernel<<<nb, THREADS, SMEM_BYTES>>>(x, batch, b1, b2, out, s_out, N);
}

// round 17
// speedup vs baseline: 1.6693x; 1.5160x over previous
#include <cuda_runtime.h>
#include <cuda_fp16.h>
#include <cstdint>

#define TN      128
#define THREADS 256
#define CC      128
#define KD      32

// uint32/float slot offsets in dynamic smem
#define XH_U    0                        // X fp16-pairs [128][68] (GEMM1 A); H fp16 overlays after GEMM1
#define XP_U    8704                     // x fp16 node-pair-packed [64][136] (stage-4 B), whole kernel
#define W1H_U   17408                    // W1^T fp16 pairs [128c][68]; ss overlays after GEMM1
#define SS_F    17408                    // logits fp32 [128][36] -> packed fp16 s pairs (in-place)
#define B1_F    26112
#define B2_F    26240
#define IB_I    26272
#define SMEM_U  26400
#define SMEM_BYTES (SMEM_U * 4)          // 105600

#define ZERO_N4 ((64 * KD * CC) / 4)     // 65536
#define R1_N    (CC * 68)                // 8704 : W1 fp16 pitch array
#define R3_N    (8 * 4 * 2 * 32)         // 2048 : W2 fp16 frags

__device__ uint32_t g_W1h[R1_N];         // pitch-68 fp16 pairs
__device__ uint32_t g_W2Hf[R3_N];        // [js][ng][e][lane] frag-linear fp16

// ---------- helpers ----------
static __device__ __forceinline__ uint32_t pk_h2(float a, float b) {
    __half2 t = __floats2half2_rn(a, b);
    return *(uint32_t*)&t;
}
static __device__ __forceinline__ void mma_f16(float* d, const uint32_t* a,
                                               uint32_t b0, uint32_t b1) {
    asm volatile(
        "mma.sync.aligned.m16n8k16.row.col.f32.f16.f16.f32 "
        "{%0,%1,%2,%3}, {%4,%5,%6,%7}, {%8,%9}, {%0,%1,%2,%3};"
        : "+f"(d[0]), "+f"(d[1]), "+f"(d[2]), "+f"(d[3])
        : "r"(a[0]), "r"(a[1]), "r"(a[2]), "r"(a[3]), "r"(b0), "r"(b1));
}

// fused: zero pooled output + weight fp16 packing
__global__ void hp_pre_kernel(float4* __restrict__ o,
                              const float* __restrict__ W1, const float* __restrict__ W2) {
    int idx = blockIdx.x * blockDim.x + threadIdx.x;
    if (idx < ZERO_N4) { o[idx] = make_float4(0.f, 0.f, 0.f, 0.f); return; }
    int i = idx - ZERO_N4;
    if (i < R1_N) {
        int c = i / 68, p = i % 68;
        uint32_t h = 0;
        if (p < 64) h = pk_h2(W1[(2 * p) * CC + c], W1[(2 * p + 1) * CC + c]);
        g_W1h[i] = h;
        return;
    }
    i -= R1_N;
    if (i < R3_N) {
        int lane = i & 31, e = (i >> 5) & 1, ng = (i >> 6) & 3, js = i >> 8;
        int qc = lane & 3, qr = lane >> 2;
        int j = 16 * js + 8 * e + 2 * qc;
        int kb = 8 * ng + qr;
        g_W2Hf[i] = pk_h2(W2[j * KD + kb], W2[(j + 1) * KD + kb]);
    }
}

__global__ __launch_bounds__(THREADS, 2)
void hp_main_kernel(const float* __restrict__ x, const int* __restrict__ batch,
                    const float* __restrict__ b1, const float* __restrict__ b2,
                    float* __restrict__ out, float* __restrict__ s_out, int N)
{
    extern __shared__ __align__(16) uint32_t smem[];
    uint32_t* XH  = smem + XH_U;                   // pitch 68 (X fp16 -> H fp16)
    uint32_t* XP  = smem + XP_U;                   // pitch 136, x node-pair fp16, persistent
    uint32_t* W1H = smem + W1H_U;                  // pitch 68
    float*    ss  = (float*)(smem + SS_F);         // pitch 36 logits -> packed fp16 s (in place)
    uint32_t* ssu = smem + SS_F;
    float*    b1s = (float*)(smem + B1_F);
    float*    b2s = (float*)(smem + B2_F);
    int*      ib  = (int*)(smem + IB_I);

    const int tid  = threadIdx.x;
    const int lane = tid & 31;
    const int wid  = tid >> 5;          // 0..7
    const int qr   = lane >> 2;         // 0..7
    const int qc   = lane & 3;          // 0..3
    const int n0   = blockIdx.x * TN;
    const int nvalid = min(TN, N - n0);

    // ================= staging: x read from global ONCE, packed both ways =================
    if (tid < TN) ib[tid] = (n0 + tid < N) ? batch[n0 + tid] : -1;
    if (tid < CC) b1s[tid] = b1[tid];
    if (tid < KD) b2s[tid] = b2[tid];
    {
        const float4* xg = (const float4*)x;
        #pragma unroll
        for (int it = 0; it < 8; ++it) {
            int idx = it * THREADS + tid;
            int p = idx >> 5, g = idx & 31;     // node pair p, channel group g
            float4 v0 = make_float4(0.f, 0.f, 0.f, 0.f);
            float4 v1 = v0;
            if (2 * p < nvalid)     v0 = xg[(size_t)(n0 + 2 * p) * 32 + g];
            if (2 * p + 1 < nvalid) v1 = xg[(size_t)(n0 + 2 * p + 1) * 32 + g];
            // node-major fp16 pairs for GEMM1 A
            *(uint2*)&XH[(2 * p) * 68 + 2 * g] =
                make_uint2(pk_h2(v0.x, v0.y), pk_h2(v0.z, v0.w));
            *(uint2*)&XH[(2 * p + 1) * 68 + 2 * g] =
                make_uint2(pk_h2(v1.x, v1.y), pk_h2(v1.z, v1.w));
            // node-pair-packed for stage-4 B
            *(uint4*)&XP[p * 136 + 4 * g] = make_uint4(
                pk_h2(v0.x, v1.x), pk_h2(v0.y, v1.y),
                pk_h2(v0.z, v1.z), pk_h2(v0.w, v1.w));
        }
        const float4* s1 = (const float4*)g_W1h;   // 2176 f4
        float4* d1 = (float4*)W1H;
        for (int i = tid; i < R1_N / 4; i += THREADS) d1[i] = s1[i];
    }
    __syncthreads();

    // ===== GEMM1: H = relu(X @ W1 + b1); single-pass fp16 k16 =====
    const int mbase = (wid >> 2) * 64;
    const int cbase = (wid & 3) * 32;
    float acc[4][4][4];
    {
        #pragma unroll
        for (int mt = 0; mt < 4; ++mt)
            #pragma unroll
            for (int nt = 0; nt < 4; ++nt)
                #pragma unroll
                for (int e = 0; e < 4; ++e) acc[mt][nt][e] = 0.f;

        for (int ks = 0; ks < 8; ++ks) {
            const int kb2 = ks * 8;
            uint32_t ah[4][4];
            #pragma unroll
            for (int mt = 0; mt < 4; ++mt) {
                int r0 = mbase + mt * 16 + qr;
                ah[mt][0] = XH[r0 * 68 + kb2 + qc];
                ah[mt][1] = XH[(r0 + 8) * 68 + kb2 + qc];
                ah[mt][2] = XH[r0 * 68 + kb2 + 4 + qc];
                ah[mt][3] = XH[(r0 + 8) * 68 + kb2 + 4 + qc];
            }
            #pragma unroll
            for (int nt = 0; nt < 4; ++nt) {
                int cb = cbase + nt * 8 + qr;
                uint32_t bh0 = W1H[cb * 68 + kb2 + qc];
                uint32_t bh1 = W1H[cb * 68 + kb2 + 4 + qc];
                #pragma unroll
                for (int mt = 0; mt < 4; ++mt)
                    mma_f16(acc[mt][nt], ah[mt], bh0, bh1);
            }
        }
    }
    __syncthreads();   // all reads of X/W1 tiles done before overlays

    // ---- epilogue 1: relu + bias, write H fp16 pairs (overlay XH) ----
    {
        #pragma unroll
        for (int mt = 0; mt < 4; ++mt) {
            int r0 = mbase + mt * 16 + qr;
            #pragma unroll
            for (int nt = 0; nt < 4; ++nt) {
                int cb = cbase + nt * 8 + 2 * qc;
                int pidx = (cbase >> 1) + nt * 4 + qc;
                float v0 = fmaxf(acc[mt][nt][0] + b1s[cb], 0.f);
                float v1 = fmaxf(acc[mt][nt][1] + b1s[cb + 1], 0.f);
                float v2 = fmaxf(acc[mt][nt][2] + b1s[cb], 0.f);
                float v3 = fmaxf(acc[mt][nt][3] + b1s[cb + 1], 0.f);
                XH[r0 * 68 + pidx]       = pk_h2(v0, v1);
                XH[(r0 + 8) * 68 + pidx] = pk_h2(v2, v3);
            }
        }
    }
    __syncthreads();

    // ===== GEMM2: logits = H @ W2 + b2; single-pass fp16; W2 frags double-buffered =====
    {
        const int r0 = wid * 16 + qr;
        float a2[4][4];
        #pragma unroll
        for (int nt = 0; nt < 4; ++nt)
            #pragma unroll
            for (int e = 0; e < 4; ++e) a2[nt][e] = 0.f;

        uint32_t whc[4][2], whn[4][2];
        #pragma unroll
        for (int nt = 0; nt < 4; ++nt) {
            whc[nt][0] = g_W2Hf[(nt * 2) * 32 + lane];
            whc[nt][1] = g_W2Hf[(nt * 2 + 1) * 32 + lane];
        }

        for (int js = 0; js < 8; ++js) {
            const int jb2 = js * 8;
            uint32_t ah[4];
            ah[0] = XH[r0 * 68 + jb2 + qc];
            ah[1] = XH[(r0 + 8) * 68 + jb2 + qc];
            ah[2] = XH[r0 * 68 + jb2 + 4 + qc];
            ah[3] = XH[(r0 + 8) * 68 + jb2 + 4 + qc];
            if (js < 7) {
                #pragma unroll
                for (int nt = 0; nt < 4; ++nt) {
                    int base = ((js + 1) * 4 + nt) * 2;
                    whn[nt][0] = g_W2Hf[base * 32 + lane];
                    whn[nt][1] = g_W2Hf[(base + 1) * 32 + lane];
                }
            }
            #pragma unroll
            for (int nt = 0; nt < 4; ++nt)
                mma_f16(a2[nt], ah, whc[nt][0], whc[nt][1]);
            #pragma unroll
            for (int nt = 0; nt < 4; ++nt) {
                whc[nt][0] = whn[nt][0];
                whc[nt][1] = whn[nt][1];
            }
        }
        #pragma unroll
        for (int nt = 0; nt < 4; ++nt) {
            int kb = nt * 8 + 2 * qc;
            *(float2*)&ss[r0 * 36 + kb] =
                make_float2(a2[nt][0] + b2s[kb], a2[nt][1] + b2s[kb + 1]);
            *(float2*)&ss[(r0 + 8) * 36 + kb] =
                make_float2(a2[nt][2] + b2s[kb], a2[nt][3] + b2s[kb + 1]);
        }
    }
    __syncthreads();

    // ===== softmax per node-pair; write packed fp16 s IN PLACE over logits =====
    {
        #pragma unroll
        for (int i8 = 0; i8 < 8; ++i8) {
            int n = wid * 16 + 2 * i8;
            float v0 = ss[n * 36 + lane];
            float v1 = ss[(n + 1) * 36 + lane];
            float m0v = v0, m1v = v1;
            #pragma unroll
            for (int o = 16; o > 0; o >>= 1) {
                m0v = fmaxf(m0v, __shfl_xor_sync(0xffffffffu, m0v, o));
                m1v = fmaxf(m1v, __shfl_xor_sync(0xffffffffu, m1v, o));
            }
            float e0 = __expf(v0 - m0v);
            float e1 = __expf(v1 - m1v);
            float s0 = e0, s1 = e1;
            #pragma unroll
            for (int o = 16; o > 0; o >>= 1) {
                s0 += __shfl_xor_sync(0xffffffffu, s0, o);
                s1 += __shfl_xor_sync(0xffffffffu, s1, o);
            }
            float sv0 = e0 / s0;
            float sv1 = e1 / s1;
            if (n < nvalid)     s_out[(size_t)(n0 + n) * KD + lane] = sv0;
            if (n + 1 < nvalid) s_out[(size_t)(n0 + n + 1) * KD + lane] = sv1;
            ssu[n * 36 + lane] = pk_h2(sv0, sv1);   // fp16 pair
        }
    }
    __syncthreads();

    // ===== stage 4 as GEMM: P[m=32][c=128] = S^T @ X per segment, 1-pass fp16 mma =====
    {
        const int mo = (wid >> 2) * 16;
        const int cq = (wid & 3) * 32;
        const int m0 = mo + qr;                  // D rows m0, m0+8
        const int bmin = ib[0];
        const int bmax = ib[nvalid - 1];
        const bool multi = (bmin != bmax);

        for (int b = bmin; b <= bmax; ++b) {
            float pacc[4][4];
            #pragma unroll
            for (int nt = 0; nt < 4; ++nt)
                #pragma unroll
                for (int e = 0; e < 4; ++e) pacc[nt][e] = 0.f;

            for (int ks = 0; ks < 8; ++ks) {
                const int pr0 = ks * 8 + qc;     // node pairs this lane touches
                const int pr1 = pr0 + 4;

                uint32_t aH[4];
                aH[0] = ssu[pr0 * 72 + m0];
                aH[1] = ssu[pr0 * 72 + m0 + 8];
                aH[2] = ssu[pr1 * 72 + m0];
                aH[3] = ssu[pr1 * 72 + m0 + 8];
                if (multi) {
                    uint32_t msk0 = (ib[2 * pr0]     != b ? 0xFFFF0000u : 0xFFFFFFFFu)
                                  & (ib[2 * pr0 + 1] != b ? 0x0000FFFFu : 0xFFFFFFFFu);
                    uint32_t msk1 = (ib[2 * pr1]     != b ? 0xFFFF0000u : 0xFFFFFFFFu)
                                  & (ib[2 * pr1 + 1] != b ? 0x0000FFFFu : 0xFFFFFFFFu);
                    aH[0] &= msk0; aH[1] &= msk0;
                    aH[2] &= msk1; aH[3] &= msk1;
                }

                #pragma unroll
                for (int nt = 0; nt < 4; ++nt) {
                    int c = cq + nt * 8 + qr;        // B column
                    uint32_t bh0 = XP[pr0 * 136 + c];
                    uint32_t bh1 = XP[pr1 * 136 + c];
                    mma_f16(pacc[nt], aH, bh0, bh1);
                }
            }
            float* ob = out + (size_t)b * (KD * CC);
            #pragma unroll
            for (int nt = 0; nt < 4; ++nt) {
                int c = cq + nt * 8 + 2 * qc;
                atomicAdd(&ob[m0 * CC + c],           pacc[nt][0]);
                atomicAdd(&ob[m0 * CC + c + 1],       pacc[nt][1]);
                atomicAdd(&ob[(m0 + 8) * CC + c],     pacc[nt][2]);
                atomicAdd(&ob[(m0 + 8) * CC + c + 1], pacc[nt][3]);
            }
        }
    }
}

extern "C" void kernel_launch(void* const* d_in, const int* in_sizes, int n_in,
                              void* d_out, int out_size)
{
    const float* x     = (const float*)d_in[0];
    const int*   batch = (const int*)d_in[1];
    const float* W1    = (const float*)d_in[2];
    const float* b1    = (const float*)d_in[3];
    const float* W2    = (const float*)d_in[4];
    const float* b2    = (const float*)d_in[5];

    const int N = in_sizes[1];
    float* out = (float*)d_out;
    size_t out_elems = (size_t)out_size - (size_t)N * KD;   // B*K*C
    float* s_out = out + out_elems;

    {   // fused zero + weight prep (one launch)
        int total = ZERO_N4 + R1_N + R3_N;
        hp_pre_kernel<<<(total + 255) / 256, 256>>>((float4*)out, W1, W2);
    }

    cudaFuncSetAttribute(hp_main_kernel,
                         cudaFuncAttributeMaxDynamicSharedMemorySize, SMEM_BYTES);
    int nb = (N + TN - 1) / TN;
    hp_main_kernel<<<nb, THREADS, SMEM_BYTES>>>(x, batch, b1, b2, out, s_out, N);
}